// round 4
// baseline (speedup 1.0000x reference)
#include <cuda_runtime.h>
#include <math.h>

// MPS log|Psi|^2, sm_103a — fp64 chain (noise floor = reference's own fp32 noise).
//  - Pair-fuse sites in fp64 (exact to 2^-53): G[g][c] = bulk[2g][:,v0,:] @ bulk[2g+1][:,v1,:]
//  - No rescaling needed: fp64 range >> chain drift (~e^+-30).
//  - 4 threads per sample; thread q owns columns {8s+2q+d}; env_i via width-4 shfl.
//  - out = 2*log|psi| in fp64, cast to fp32.

#define NSITES  256
#define BATCH   8192
#define NGROUP  127

__device__ double       g_G[(size_t)NGROUP * 4 * 4096];   // 16.6 MB fused-pair table
__device__ unsigned int g_bits[BATCH * 8];                // packed config bits

// ---------------------------------------------------------------- bit packing
__global__ void pack_bits_kernel(const int* __restrict__ cfg) {
    int t = blockIdx.x * blockDim.x + threadIdx.x;   // 0 .. 65535
    int row = t >> 3, w = t & 7;
    const int* p = cfg + row * NSITES + w * 32;
    unsigned int v = 0;
#pragma unroll
    for (int b = 0; b < 32; b++) v |= ((unsigned int)p[b] & 1u) << b;
    g_bits[row * 8 + w] = v;
}

// ------------------------------------------------- fp64 pair-product G table
// blockIdx.x = group g (0..126), blockIdx.y = c (0..3). 256 threads.
__global__ void build_G_kernel(const float* __restrict__ bulk) {
    __shared__ float As[64 * 64];
    __shared__ float Bs[64 * 68];
    int g = blockIdx.x, c = blockIdx.y;
    int v0 = c & 1, v1 = (c >> 1) & 1;
    int tid = threadIdx.x;
    // bulk[t][i][v][j] at t*8192 + i*128 + v*64 + j
    const float* A = bulk + (size_t)(2 * g) * 8192 + v0 * 64;
    const float* B = bulk + (size_t)(2 * g + 1) * 8192 + v1 * 64;
    for (int n = tid; n < 4096; n += 256) {
        int i = n >> 6, j = n & 63;
        As[i * 64 + j] = A[i * 128 + j];
        Bs[i * 68 + j] = B[i * 128 + j];
    }
    __syncthreads();
    int r  = tid >> 2;            // output row
    int j0 = (tid & 3) * 16;      // output col block
    double acc[16];
#pragma unroll
    for (int q = 0; q < 16; q++) acc[q] = 0.0;
#pragma unroll 8
    for (int k = 0; k < 64; k++) {
        double a = (double)As[r * 64 + k];
#pragma unroll
        for (int q = 0; q < 16; q++) acc[q] = fma(a, (double)Bs[k * 68 + j0 + q], acc[q]);
    }
    double* dst = g_G + ((size_t)(g * 4 + c) << 12) + r * 64 + j0;
#pragma unroll
    for (int q = 0; q < 16; q++) dst[q] = acc[q];
}

// --------------------------------------------------------------- main chain
__global__ __launch_bounds__(256, 1)
void mps_main_kernel(const float* __restrict__ left,
                     const float* __restrict__ right,
                     float* __restrict__ out) {
    const int tid = threadIdx.x;
    const int q   = tid & 3;                    // quad lane
    const int row = blockIdx.x * 64 + (tid >> 2);

    unsigned int B[8];
#pragma unroll
    for (int w = 0; w < 8; w++) B[w] = g_bits[row * 8 + w];
#define BIT(s) ((B[(s) >> 5] >> ((s) & 31)) & 1u)

    // env init from left[0, cfg[:,0], :]; thread q owns j = 8s + 2q + d
    double env[16];
    {
        unsigned int b0 = BIT(0);
#pragma unroll
        for (int s = 0; s < 8; s++) {
            env[2 * s + 0] = (double)left[b0 * 64 + 8 * s + 2 * q + 0];
            env[2 * s + 1] = (double)left[b0 * 64 + 8 * s + 2 * q + 1];
        }
    }

    for (int g = 0; g < NGROUP; g++) {
        unsigned int c = BIT(2 * g + 1) | (BIT(2 * g + 2) << 1);
        const double2* __restrict__ Gm =
            (const double2*)(g_G + ((size_t)(g * 4 + c) << 12));

        double2 acc[8];
#pragma unroll
        for (int s = 0; s < 8; s++) { acc[s].x = 0.0; acc[s].y = 0.0; }

#pragma unroll
        for (int i = 0; i < 64; i++) {
            // owner of env index i within the quad: q = (i>>1)&3, reg = ((i>>3)<<1)|(i&1)
            double e = __shfl_sync(0xFFFFFFFFu,
                                   env[((i >> 3) << 1) | (i & 1)],
                                   (i >> 1) & 3, 4);
            const double2* rp = Gm + (i << 5) + q;      // row i, this lane's chunks
#pragma unroll
            for (int s = 0; s < 8; s++) {
                double2 gv = rp[s * 4];                 // j = 8s + 2q (+1)
                acc[s].x = fma(e, gv.x, acc[s].x);
                acc[s].y = fma(e, gv.y, acc[s].y);
            }
        }
#pragma unroll
        for (int s = 0; s < 8; s++) {
            env[2 * s + 0] = acc[s].x;
            env[2 * s + 1] = acc[s].y;
        }
    }

    // final contraction with right[:, cfg[:,-1], 0]
    unsigned int bl = BIT(255);
    double part = 0.0;
#pragma unroll
    for (int s = 0; s < 8; s++) {
        part = fma(env[2 * s + 0], (double)right[(8 * s + 2 * q + 0) * 2 + bl], part);
        part = fma(env[2 * s + 1], (double)right[(8 * s + 2 * q + 1) * 2 + bl], part);
    }
    // quad reduction (quads are lane-aligned, xor 1/2 stay inside)
    part += __shfl_xor_sync(0xFFFFFFFFu, part, 1);
    part += __shfl_xor_sync(0xFFFFFFFFu, part, 2);

    if (q == 0) {
        double ap = fabs(part);
        if (ap < 1e-300) ap = 1e-300;
        out[row] = (float)(2.0 * log(ap));
    }
#undef BIT
}

// ------------------------------------------------------------------- launch
extern "C" void kernel_launch(void* const* d_in, const int* in_sizes, int n_in,
                              void* d_out, int out_size) {
    const int*   cfg   = (const int*)d_in[0];
    const float* left  = (const float*)d_in[1];
    const float* bulk  = (const float*)d_in[2];
    const float* right = (const float*)d_in[3];
    float*       out   = (float*)d_out;

    pack_bits_kernel<<<BATCH * 8 / 256, 256>>>(cfg);
    dim3 gg(NGROUP, 4);
    build_G_kernel<<<gg, 256>>>(bulk);
    mps_main_kernel<<<BATCH / 64, 256>>>(left, right, out);
}

// round 5
// speedup vs baseline: 2.6419x; 2.6419x over previous
#include <cuda_runtime.h>
#include <math.h>

// MPS log|Psi|^2, sm_103a — double-float (hi,lo fp32) chain on the FMA pipe.
// R4 showed the fp64 pipe is ~1.74 lane-DFMA/cyc/SM → 8.8 ms is its roofline.
// Same exact-arithmetic strategy (noise ~2^-45 per site, far below the
// reference's own fp32 noise), but executed as compensated fp32:
//   product: p = eh*gh exact-split via FMA (e1), cross terms eh*gl + el*gh,
//   sum of p via Kahan; all packed 2-wide with fma.rn.f32x2.
// Pair-fused G table stored as two planes (hi, lo). Exact pow2 rescale per
// group (fp32 range). Final dot + log in fp64 (one-shot, cancellation-safe).

#define NSITES  256
#define BATCH   8192
#define NGROUP  127
#define SPC     56            // samples per CTA; 147*56 = 8232 >= 8192
#define SGN64   0x8000000080000000ULL

__device__ float        g_Gh[(size_t)NGROUP * 4 * 4096];   // hi plane, 8.3 MB
__device__ float        g_Gl[(size_t)NGROUP * 4 * 4096];   // lo plane, 8.3 MB
__device__ unsigned int g_bits[BATCH * 8];

typedef unsigned long long ull;

__device__ __forceinline__ ull f2x_mul(ull a, ull b) {
    ull d; asm("mul.rn.f32x2 %0, %1, %2;" : "=l"(d) : "l"(a), "l"(b)); return d;
}
__device__ __forceinline__ ull f2x_add(ull a, ull b) {
    ull d; asm("add.rn.f32x2 %0, %1, %2;" : "=l"(d) : "l"(a), "l"(b)); return d;
}
__device__ __forceinline__ ull f2x_fma(ull a, ull b, ull c) {
    ull d; asm("fma.rn.f32x2 %0, %1, %2, %3;" : "=l"(d) : "l"(a), "l"(b), "l"(c)); return d;
}
__device__ __forceinline__ ull packff(float x, float y) {
    ull d; asm("mov.b64 %0, {%1, %2};" : "=l"(d) : "f"(x), "f"(y)); return d;
}
__device__ __forceinline__ void unpackff(ull v, float& x, float& y) {
    asm("mov.b64 {%0, %1}, %2;" : "=f"(x), "=f"(y) : "l"(v));
}

// ---------------------------------------------------------------- bit packing
__global__ void pack_bits_kernel(const int* __restrict__ cfg) {
    int t = blockIdx.x * blockDim.x + threadIdx.x;
    int row = t >> 3, w = t & 7;
    const int* p = cfg + row * NSITES + w * 32;
    unsigned int v = 0;
#pragma unroll
    for (int b = 0; b < 32; b++) v |= ((unsigned int)p[b] & 1u) << b;
    g_bits[row * 8 + w] = v;
}

// --------------------------- pair-product table, compensated fp32, (hi,lo) out
// blockIdx.x = group g, blockIdx.y = c. 256 threads.
__global__ void build_G_kernel(const float* __restrict__ bulk) {
    __shared__ float As[64 * 64];
    __shared__ float Bs[64 * 68];
    int g = blockIdx.x, c = blockIdx.y;
    int v0 = c & 1, v1 = (c >> 1) & 1;
    int tid = threadIdx.x;
    const float* A = bulk + (size_t)(2 * g) * 8192 + v0 * 64;     // bulk[2g][i][v0][j]
    const float* B = bulk + (size_t)(2 * g + 1) * 8192 + v1 * 64;
    for (int n = tid; n < 4096; n += 256) {
        int i = n >> 6, j = n & 63;
        As[i * 64 + j] = A[i * 128 + j];
        Bs[i * 68 + j] = B[i * 128 + j];
    }
    __syncthreads();
    int r  = tid >> 2;
    int j0 = (tid & 3) * 16;
    float s[16], cc[16], ae[16];
#pragma unroll
    for (int q = 0; q < 16; q++) { s[q] = 0.f; cc[q] = 0.f; ae[q] = 0.f; }
#pragma unroll 8
    for (int k = 0; k < 64; k++) {
        float a = As[r * 64 + k];
#pragma unroll
        for (int q = 0; q < 16; q++) {
            float b  = Bs[k * 68 + j0 + q];
            float p  = a * b;
            float e1 = fmaf(a, b, -p);          // exact product error
            float y  = p - cc[q];               // Kahan
            float t  = s[q] + y;
            cc[q]    = (t - s[q]) - y;
            s[q]     = t;
            ae[q]   += e1;
        }
    }
    size_t base = ((size_t)(g * 4 + c) << 12) + r * 64 + j0;
#pragma unroll
    for (int q = 0; q < 16; q++) {
        float lo = ae[q] - cc[q];
        float H  = s[q] + lo;                   // Fast2Sum
        float L  = (s[q] - H) + lo;
        g_Gh[base + q] = H;
        g_Gl[base + q] = L;
    }
}

// --------------------------------------------------------------- main chain
__global__ __launch_bounds__(224, 1)
void mps_main_kernel(const float* __restrict__ left,
                     const float* __restrict__ right,
                     float* __restrict__ out) {
    const int tid = threadIdx.x;
    const int q   = tid & 3;                    // quad lane: owns j in [16q,16q+16)
    const int row0 = blockIdx.x * SPC + (tid >> 2);
    const int row  = row0 < BATCH ? row0 : BATCH - 1;

    unsigned int B[8];
#pragma unroll
    for (int w = 0; w < 8; w++) B[w] = g_bits[row * 8 + w];
#define BIT(s) ((B[(s) >> 5] >> ((s) & 31)) & 1u)

    float envh[16], envl[16];
    {
        unsigned int b0 = BIT(0);
#pragma unroll
        for (int t = 0; t < 16; t++) {
            envh[t] = left[b0 * 64 + 16 * q + t];
            envl[t] = 0.0f;
        }
    }
    int ls2 = 0;

    for (int g = 0; g < NGROUP; g++) {
        unsigned int c = BIT(2 * g + 1) | (BIT(2 * g + 2) << 1);
        const float* __restrict__ Gh = g_Gh + ((size_t)(g * 4 + c) << 12);
        const float* __restrict__ Gl = g_Gl + ((size_t)(g * 4 + c) << 12);

        ull s[8], nc[8], ae[8];
#pragma unroll
        for (int u = 0; u < 8; u++) { s[u] = 0ULL; nc[u] = 0ULL; ae[u] = 0ULL; }

#pragma unroll
        for (int i = 0; i < 64; i++) {
            float eh = __shfl_sync(0xFFFFFFFFu, envh[i & 15], i >> 4, 4);
            float el = __shfl_sync(0xFFFFFFFFu, envl[i & 15], i >> 4, 4);
            ull ep  = packff(eh, eh);
            ull elp = packff(el, el);
            const float4* Hr = (const float4*)(Gh + (i << 6) + (q << 4));
            const float4* Lr = (const float4*)(Gl + (i << 6) + (q << 4));
#pragma unroll
            for (int v = 0; v < 4; v++) {
                float4 hv = Hr[v];
                float4 lv = Lr[v];
                ull h2[2] = { packff(hv.x, hv.y), packff(hv.z, hv.w) };
                ull l2[2] = { packff(lv.x, lv.y), packff(lv.z, lv.w) };
#pragma unroll
                for (int w = 0; w < 2; w++) {
                    int u = 2 * v + w;
                    ull p  = f2x_mul(ep, h2[w]);
                    ull e1 = f2x_fma(ep, h2[w], p ^ SGN64);     // exact prod error
                    ae[u]  = f2x_fma(elp, h2[w], ae[u]);        // el*gh
                    ae[u]  = f2x_fma(ep,  l2[w], ae[u]);        // eh*gl
                    ae[u]  = f2x_add(ae[u], e1);
                    ull y  = f2x_add(p, nc[u]);                 // p - c
                    ull t  = f2x_add(s[u], y);
                    nc[u]  = f2x_add(f2x_add(s[u], t ^ SGN64), y); // -(new c)
                    s[u]   = t;
                }
            }
        }

        // fold: total = s + nc + ae  →  (H, L) pair per column
        float m = 0.0f;
#pragma unroll
        for (int u = 0; u < 8; u++) {
            ull lo = f2x_add(ae[u], nc[u]);
            ull H  = f2x_add(s[u], lo);
            ull L  = f2x_add(f2x_add(s[u], H ^ SGN64), lo);
            unpackff(H, envh[2 * u], envh[2 * u + 1]);
            unpackff(L, envl[2 * u], envl[2 * u + 1]);
            m = fmaxf(m, fmaxf(fabsf(envh[2 * u]), fabsf(envh[2 * u + 1])));
        }

        // exact power-of-2 rescale (quad-wide max)
        m = fmaxf(m, __shfl_xor_sync(0xFFFFFFFFu, m, 1));
        m = fmaxf(m, __shfl_xor_sync(0xFFFFFFFFu, m, 2));
        int ef = (int)(__float_as_uint(m) >> 23);
        if (ef > 0) {
            ls2 += ef - 127;
            float sc = __uint_as_float((unsigned int)(254 - ef) << 23);
#pragma unroll
            for (int t = 0; t < 16; t++) { envh[t] *= sc; envl[t] *= sc; }
        }
    }

    // final contraction in fp64 (cancellation-sensitive, one-shot)
    unsigned int bl = BIT(255);
    double part = 0.0;
#pragma unroll
    for (int t = 0; t < 16; t++) {
        double e = (double)envh[t] + (double)envl[t];
        part = fma(e, (double)right[(16 * q + t) * 2 + bl], part);
    }
    part += __shfl_xor_sync(0xFFFFFFFFu, part, 1);
    part += __shfl_xor_sync(0xFFFFFFFFu, part, 2);

    if (q == 0 && row0 < BATCH) {
        double ap = fabs(part);
        if (ap < 1e-300) ap = 1e-300;
        out[row0] = (float)(2.0 * (log(ap) + (double)ls2 * 0.6931471805599453094));
    }
#undef BIT
}

// ------------------------------------------------------------------- launch
extern "C" void kernel_launch(void* const* d_in, const int* in_sizes, int n_in,
                              void* d_out, int out_size) {
    const int*   cfg   = (const int*)d_in[0];
    const float* left  = (const float*)d_in[1];
    const float* bulk  = (const float*)d_in[2];
    const float* right = (const float*)d_in[3];
    float*       out   = (float*)d_out;

    pack_bits_kernel<<<BATCH * 8 / 256, 256>>>(cfg);
    dim3 gg(NGROUP, 4);
    build_G_kernel<<<gg, 256>>>(bulk);
    mps_main_kernel<<<(BATCH + SPC - 1) / SPC, 224>>>(left, right, out);
}

// round 7
// speedup vs baseline: 5.5906x; 2.1161x over previous
#include <cuda_runtime.h>
#include <math.h>

// MPS log|Psi|^2, sm_103a — Kahan-compensated fp32 chain + e1 product capture.
//  - G = pair-fused site products (127 groups x 4 combos), compensated build,
//    stored correctly-rounded fp32 (one plane, 8.3 MB).
//  - Chain per group: env fp32, Kahan sum (robust to ordering) + exact
//    product-error capture (e1 via FMA) into a lo accumulator.
//  - 8 threads/sample; thread o owns cols {4o..4o+3} u {32+4o..32+4o+3}
//    (each octet LDG.128 = one contiguous 128B line). env_i via width-8 shfl.
//  - Exact pow2 rescale per group; final dot + log in fp64.

#define NSITES  256
#define BATCH   8192
#define NGROUP  127
#define SPC     56                 // samples per CTA: 147*56 = 8232 >= 8192
#define SGN64   0x8000000080000000ULL

__device__ float        g_Gh[(size_t)NGROUP * 4 * 4096];
__device__ unsigned int g_bits[BATCH * 8];

typedef unsigned long long ull;

__device__ __forceinline__ ull f2x_mul(ull a, ull b) {
    ull d; asm("mul.rn.f32x2 %0, %1, %2;" : "=l"(d) : "l"(a), "l"(b)); return d;
}
__device__ __forceinline__ ull f2x_add(ull a, ull b) {
    ull d; asm("add.rn.f32x2 %0, %1, %2;" : "=l"(d) : "l"(a), "l"(b)); return d;
}
__device__ __forceinline__ ull f2x_fma(ull a, ull b, ull c) {
    ull d; asm("fma.rn.f32x2 %0, %1, %2, %3;" : "=l"(d) : "l"(a), "l"(b), "l"(c)); return d;
}
__device__ __forceinline__ ull packff(float x, float y) {
    ull d; asm("mov.b64 %0, {%1, %2};" : "=l"(d) : "f"(x), "f"(y)); return d;
}
__device__ __forceinline__ void unpackff(ull v, float& x, float& y) {
    asm("mov.b64 {%0, %1}, %2;" : "=f"(x), "=f"(y) : "l"(v));
}

// ---------------------------------------------------------------- bit packing
__global__ void pack_bits_kernel(const int* __restrict__ cfg) {
    int t = blockIdx.x * blockDim.x + threadIdx.x;
    int row = t >> 3, w = t & 7;
    const int* p = cfg + row * NSITES + w * 32;
    unsigned int v = 0;
#pragma unroll
    for (int b = 0; b < 32; b++) v |= ((unsigned int)p[b] & 1u) << b;
    g_bits[row * 8 + w] = v;
}

// ------------- pair-product table, compensated, correctly-rounded fp32 output
__global__ void build_G_kernel(const float* __restrict__ bulk) {
    __shared__ float As[64 * 64];
    __shared__ float Bs[64 * 68];
    int g = blockIdx.x, c = blockIdx.y;
    int v0 = c & 1, v1 = (c >> 1) & 1;
    int tid = threadIdx.x;
    const float* A = bulk + (size_t)(2 * g) * 8192 + v0 * 64;   // bulk[2g][i][v0][j]
    const float* B = bulk + (size_t)(2 * g + 1) * 8192 + v1 * 64;
    for (int n = tid; n < 4096; n += 256) {
        int i = n >> 6, j = n & 63;
        As[i * 64 + j] = A[i * 128 + j];
        Bs[i * 68 + j] = B[i * 128 + j];
    }
    __syncthreads();
    int r  = tid >> 2;
    int j0 = (tid & 3) * 16;
    float s[16], cc[16], ae[16];
#pragma unroll
    for (int q = 0; q < 16; q++) { s[q] = 0.f; cc[q] = 0.f; ae[q] = 0.f; }
#pragma unroll 8
    for (int k = 0; k < 64; k++) {
        float a = As[r * 64 + k];
#pragma unroll
        for (int q = 0; q < 16; q++) {
            float b  = Bs[k * 68 + j0 + q];
            float p  = a * b;
            float e1 = fmaf(a, b, -p);
            float y  = p - cc[q];
            float t  = s[q] + y;
            cc[q]    = (t - s[q]) - y;
            s[q]     = t;
            ae[q]   += e1;
        }
    }
    size_t base = ((size_t)(g * 4 + c) << 12) + r * 64 + j0;
#pragma unroll
    for (int q = 0; q < 16; q++)
        g_Gh[base + q] = s[q] + (ae[q] - cc[q]);    // ~correctly rounded
}

// --------------------------------------------------------------- main chain
__global__ __launch_bounds__(8 * SPC, 1)
void mps_main_kernel(const float* __restrict__ left,
                     const float* __restrict__ right,
                     float* __restrict__ out) {
    const int tid  = threadIdx.x;
    const int o    = tid & 7;                    // octet lane
    const int row0 = blockIdx.x * SPC + (tid >> 3);
    const int row  = row0 < BATCH ? row0 : BATCH - 1;

    unsigned int B[8];
#pragma unroll
    for (int w = 0; w < 8; w++) B[w] = g_bits[row * 8 + w];
#define BIT(s) ((B[(s) >> 5] >> ((s) & 31)) & 1u)
    // column owned by (o, reg r): r<4 -> 4o+r ; r>=4 -> 32+4o+(r-4)
#define COL(r) (((r) < 4) ? (4 * o + (r)) : (32 + 4 * o + (r) - 4))

    float env[8];
    {
        unsigned int b0 = BIT(0);
#pragma unroll
        for (int t = 0; t < 8; t++) env[t] = left[b0 * 64 + COL(t)];
    }
    int ls2 = 0;

    for (int g = 0; g < NGROUP; g++) {
        unsigned int c = BIT(2 * g + 1) | (BIT(2 * g + 2) << 1);
        const float* __restrict__ Gm = g_Gh + ((size_t)(g * 4 + c) << 12) + 4 * o;

        ull s[4], nc[4], lo[4];
#pragma unroll
        for (int u = 0; u < 4; u++) { s[u] = 0ULL; nc[u] = 0ULL; lo[u] = 0ULL; }

#pragma unroll
        for (int half = 0; half < 2; half++) {
            for (int blk = 0; blk < 8; blk++) {          // runtime loop (I$)
#pragma unroll
                for (int r = 0; r < 4; r++) {
                    int i = half * 32 + blk * 4 + r;     // env index / G row
                    float eh = __shfl_sync(0xFFFFFFFFu, env[half * 4 + r], blk, 8);
                    ull ep = packff(eh, eh);
                    const float4* R0 = (const float4*)(Gm + (i << 6));
                    const float4* R1 = (const float4*)(Gm + (i << 6) + 32);
                    float4 h0 = R0[0];
                    float4 h1 = R1[0];
                    ull h2[4] = { packff(h0.x, h0.y), packff(h0.z, h0.w),
                                  packff(h1.x, h1.y), packff(h1.z, h1.w) };
#pragma unroll
                    for (int u = 0; u < 4; u++) {
                        ull p  = f2x_mul(ep, h2[u]);
                        ull e1 = f2x_fma(ep, h2[u], p ^ SGN64);
                        lo[u]  = f2x_add(lo[u], e1);
                        ull y  = f2x_add(p, nc[u]);               // p - c
                        ull t  = f2x_add(s[u], y);
                        nc[u]  = f2x_add(f2x_add(s[u], t ^ SGN64), y);
                        s[u]   = t;
                    }
                }
            }
        }

        // fold s + nc + lo -> env; track octet max
        float m = 0.0f;
#pragma unroll
        for (int u = 0; u < 4; u++) {
            ull tot = f2x_add(s[u], f2x_add(nc[u], lo[u]));
            unpackff(tot, env[2 * u], env[2 * u + 1]);
            m = fmaxf(m, fmaxf(fabsf(env[2 * u]), fabsf(env[2 * u + 1])));
        }

        // exact power-of-2 rescale (octet-wide max)
        m = fmaxf(m, __shfl_xor_sync(0xFFFFFFFFu, m, 1));
        m = fmaxf(m, __shfl_xor_sync(0xFFFFFFFFu, m, 2));
        m = fmaxf(m, __shfl_xor_sync(0xFFFFFFFFu, m, 4));
        int ef = (int)(__float_as_uint(m) >> 23);
        if (ef > 0) {
            ls2 += ef - 127;
            float sc = __uint_as_float((unsigned int)(254 - ef) << 23);
#pragma unroll
            for (int t = 0; t < 8; t++) env[t] *= sc;
        }
    }

    // final contraction in fp64 (cancellation-sensitive, one-shot)
    unsigned int bl = BIT(255);
    double part = 0.0;
#pragma unroll
    for (int t = 0; t < 8; t++)
        part = fma((double)env[t], (double)right[COL(t) * 2 + bl], part);
    part += __shfl_xor_sync(0xFFFFFFFFu, part, 1);
    part += __shfl_xor_sync(0xFFFFFFFFu, part, 2);
    part += __shfl_xor_sync(0xFFFFFFFFu, part, 4);

    if (o == 0 && row0 < BATCH) {
        double ap = fabs(part);
        if (ap < 1e-300) ap = 1e-300;
        out[row0] = (float)(2.0 * (log(ap) + (double)ls2 * 0.6931471805599453094));
    }
#undef COL
#undef BIT
}

// ------------------------------------------------------------------- launch
extern "C" void kernel_launch(void* const* d_in, const int* in_sizes, int n_in,
                              void* d_out, int out_size) {
    const int*   cfg   = (const int*)d_in[0];
    const float* left  = (const float*)d_in[1];
    const float* bulk  = (const float*)d_in[2];
    const float* right = (const float*)d_in[3];
    float*       out   = (float*)d_out;

    pack_bits_kernel<<<BATCH * 8 / 256, 256>>>(cfg);
    dim3 gg(NGROUP, 4);
    build_G_kernel<<<gg, 256>>>(bulk);
    mps_main_kernel<<<(BATCH + SPC - 1) / SPC, 8 * SPC>>>(left, right, out);
}

// round 11
// speedup vs baseline: 7.5613x; 1.3525x over previous
#include <cuda_runtime.h>
#include <math.h>

// MPS log|Psi|^2, sm_103a — R7 numerics (pair fusion + e1 + Kahan), but
// 16 threads/sample for 2x warp occupancy (896 thr/SM, 7 warps/SMSP).
// R7 was ~3x latency-exposed at 3.5 warps/SMSP with serial Kahan chains;
// per-column summation order is preserved bit-for-bit, so rel_err stays
// at R7's proven 4.17e-4.

#define NSITES  256
#define BATCH   8192
#define NGROUP  127
#define SPC     56                 // samples per CTA: 147*56 = 8232 >= 8192
#define SGN64   0x8000000080000000ULL

__device__ float        g_Gh[(size_t)NGROUP * 4 * 4096];
__device__ unsigned int g_bits[BATCH * 8];

typedef unsigned long long ull;

__device__ __forceinline__ ull f2x_mul(ull a, ull b) {
    ull d; asm("mul.rn.f32x2 %0, %1, %2;" : "=l"(d) : "l"(a), "l"(b)); return d;
}
__device__ __forceinline__ ull f2x_add(ull a, ull b) {
    ull d; asm("add.rn.f32x2 %0, %1, %2;" : "=l"(d) : "l"(a), "l"(b)); return d;
}
__device__ __forceinline__ ull f2x_fma(ull a, ull b, ull c) {
    ull d; asm("fma.rn.f32x2 %0, %1, %2, %3;" : "=l"(d) : "l"(a), "l"(b), "l"(c)); return d;
}
__device__ __forceinline__ ull packff(float x, float y) {
    ull d; asm("mov.b64 %0, {%1, %2};" : "=l"(d) : "f"(x), "f"(y)); return d;
}
__device__ __forceinline__ void unpackff(ull v, float& x, float& y) {
    asm("mov.b64 {%0, %1}, %2;" : "=f"(x), "=f"(y) : "l"(v));
}

// ---------------------------------------------------------------- bit packing
__global__ void pack_bits_kernel(const int* __restrict__ cfg) {
    int t = blockIdx.x * blockDim.x + threadIdx.x;
    int row = t >> 3, w = t & 7;
    const int* p = cfg + row * NSITES + w * 32;
    unsigned int v = 0;
#pragma unroll
    for (int b = 0; b < 32; b++) v |= ((unsigned int)p[b] & 1u) << b;
    g_bits[row * 8 + w] = v;
}

// ------------- pair-product table, compensated, correctly-rounded fp32 output
__global__ void build_G_kernel(const float* __restrict__ bulk) {
    __shared__ float As[64 * 65];
    __shared__ float Bs[64 * 68];
    int g = blockIdx.x, c = blockIdx.y;
    int v0 = c & 1, v1 = (c >> 1) & 1;
    int tid = threadIdx.x;
    const float* A = bulk + (size_t)(2 * g) * 8192 + v0 * 64;   // bulk[2g][i][v0][j]
    const float* B = bulk + (size_t)(2 * g + 1) * 8192 + v1 * 64;
    for (int n = tid; n < 4096; n += 256) {
        int i = n >> 6, j = n & 63;
        As[i * 65 + j] = A[i * 128 + j];
        Bs[i * 68 + j] = B[i * 128 + j];
    }
    __syncthreads();
    int r  = tid >> 2;
    int j0 = (tid & 3) * 16;
    float s[16], cc[16], ae[16];
#pragma unroll
    for (int q = 0; q < 16; q++) { s[q] = 0.f; cc[q] = 0.f; ae[q] = 0.f; }
#pragma unroll 8
    for (int k = 0; k < 64; k++) {
        float a = As[r * 65 + k];
#pragma unroll
        for (int q = 0; q < 16; q++) {
            float b  = Bs[k * 68 + j0 + q];
            float p  = a * b;
            float e1 = fmaf(a, b, -p);
            float y  = p - cc[q];
            float t  = s[q] + y;
            cc[q]    = (t - s[q]) - y;
            s[q]     = t;
            ae[q]   += e1;
        }
    }
    size_t base = ((size_t)(g * 4 + c) << 12) + r * 64 + j0;
#pragma unroll
    for (int q = 0; q < 16; q++)
        g_Gh[base + q] = s[q] + (ae[q] - cc[q]);    // ~correctly rounded
}

// --------------------------------------------------------------- main chain
__global__ __launch_bounds__(16 * SPC, 1)
void mps_main_kernel(const float* __restrict__ left,
                     const float* __restrict__ right,
                     float* __restrict__ out) {
    const int tid  = threadIdx.x;
    const int o    = tid & 15;                   // 16-group lane: cols [4o,4o+4)
    const int row0 = blockIdx.x * SPC + (tid >> 4);
    const int row  = row0 < BATCH ? row0 : BATCH - 1;

    unsigned int B[8];
#pragma unroll
    for (int w = 0; w < 8; w++) B[w] = g_bits[row * 8 + w];
#define BIT(s) ((B[(s) >> 5] >> ((s) & 31)) & 1u)

    float env[4];
    {
        unsigned int b0 = BIT(0);
#pragma unroll
        for (int t = 0; t < 4; t++) env[t] = left[b0 * 64 + 4 * o + t];
    }
    int ls2 = 0;

    for (int g = 0; g < NGROUP; g++) {
        unsigned int c = BIT(2 * g + 1) | (BIT(2 * g + 2) << 1);
        const float* __restrict__ Gm = g_Gh + ((size_t)(g * 4 + c) << 12) + 4 * o;

        ull s[2], nc[2], lo[2];
#pragma unroll
        for (int u = 0; u < 2; u++) { s[u] = 0ULL; nc[u] = 0ULL; lo[u] = 0ULL; }

        for (int blk = 0; blk < 16; blk++) {             // runtime loop (I$)
#pragma unroll
            for (int r = 0; r < 4; r++) {
                int i = blk * 4 + r;                     // env index / G row
                float eh = __shfl_sync(0xFFFFFFFFu, env[r], blk, 16);
                ull ep = packff(eh, eh);
                float4 h0 = *(const float4*)(Gm + (i << 6));
                ull h2[2] = { packff(h0.x, h0.y), packff(h0.z, h0.w) };
#pragma unroll
                for (int u = 0; u < 2; u++) {
                    ull p  = f2x_mul(ep, h2[u]);
                    ull e1 = f2x_fma(ep, h2[u], p ^ SGN64);        // exact prod err
                    lo[u]  = f2x_add(lo[u], e1);
                    ull y  = f2x_add(p, nc[u]);                    // p - c
                    ull t  = f2x_add(s[u], y);
                    nc[u]  = f2x_add(f2x_add(s[u], t ^ SGN64), y); // -(new c)
                    s[u]   = t;
                }
            }
        }

        // fold s + nc + lo -> env; track group max (same order as R7)
        float m = 0.0f;
#pragma unroll
        for (int u = 0; u < 2; u++) {
            ull tot = f2x_add(s[u], f2x_add(nc[u], lo[u]));
            unpackff(tot, env[2 * u], env[2 * u + 1]);
            m = fmaxf(m, fmaxf(fabsf(env[2 * u]), fabsf(env[2 * u + 1])));
        }

        // exact power-of-2 rescale (16-lane max, width-16 shfl stays in-sample)
        m = fmaxf(m, __shfl_xor_sync(0xFFFFFFFFu, m, 1, 16));
        m = fmaxf(m, __shfl_xor_sync(0xFFFFFFFFu, m, 2, 16));
        m = fmaxf(m, __shfl_xor_sync(0xFFFFFFFFu, m, 4, 16));
        m = fmaxf(m, __shfl_xor_sync(0xFFFFFFFFu, m, 8, 16));
        int ef = (int)(__float_as_uint(m) >> 23);
        if (ef > 0) {
            ls2 += ef - 127;
            float sc = __uint_as_float((unsigned int)(254 - ef) << 23);
#pragma unroll
            for (int t = 0; t < 4; t++) env[t] *= sc;
        }
    }

    // final contraction in fp64 (cancellation-sensitive, one-shot)
    unsigned int bl = BIT(255);
    double part = 0.0;
#pragma unroll
    for (int t = 0; t < 4; t++)
        part = fma((double)env[t], (double)right[(4 * o + t) * 2 + bl], part);
    part += __shfl_xor_sync(0xFFFFFFFFu, part, 1, 16);
    part += __shfl_xor_sync(0xFFFFFFFFu, part, 2, 16);
    part += __shfl_xor_sync(0xFFFFFFFFu, part, 4, 16);
    part += __shfl_xor_sync(0xFFFFFFFFu, part, 8, 16);

    if (o == 0 && row0 < BATCH) {
        double ap = fabs(part);
        if (ap < 1e-300) ap = 1e-300;
        out[row0] = (float)(2.0 * (log(ap) + (double)ls2 * 0.6931471805599453094));
    }
#undef BIT
}

// ------------------------------------------------------------------- launch
extern "C" void kernel_launch(void* const* d_in, const int* in_sizes, int n_in,
                              void* d_out, int out_size) {
    const int*   cfg   = (const int*)d_in[0];
    const float* left  = (const float*)d_in[1];
    const float* bulk  = (const float*)d_in[2];
    const float* right = (const float*)d_in[3];
    float*       out   = (float*)d_out;

    pack_bits_kernel<<<BATCH * 8 / 256, 256>>>(cfg);
    dim3 gg(NGROUP, 4);
    build_G_kernel<<<gg, 256>>>(bulk);
    mps_main_kernel<<<(BATCH + SPC - 1) / SPC, 16 * SPC>>>(left, right, out);
}

// round 14
// speedup vs baseline: 7.5802x; 1.0025x over previous
#include <cuda_runtime.h>
#include <math.h>

// MPS log|Psi|^2, sm_103a — R11 numerics BIT-EXACT (pair fusion + e1 + Kahan,
// packed f32x2, 16 threads/sample), plus zero-numerics scheduling changes:
//  - full 64-row unroll (removes runtime-loop overhead, batches load issue)
//  - prefetch.global.L1 of the next group's first table lines issued early
//    in the current group (combo index is register-only), hiding the L2
//    cold-miss burst at each group boundary.
// Arithmetic order is IDENTICAL to R11 -> rel_err must be 4.171494e-4.

#define NSITES  256
#define BATCH   8192
#define NGROUP  127
#define SPC     56                 // samples per CTA: 147*56 = 8232 >= 8192
#define SGN64   0x8000000080000000ULL

__device__ float        g_Gh[(size_t)NGROUP * 4 * 4096];
__device__ unsigned int g_bits[BATCH * 8];

typedef unsigned long long ull;

__device__ __forceinline__ ull f2x_mul(ull a, ull b) {
    ull d; asm("mul.rn.f32x2 %0, %1, %2;" : "=l"(d) : "l"(a), "l"(b)); return d;
}
__device__ __forceinline__ ull f2x_add(ull a, ull b) {
    ull d; asm("add.rn.f32x2 %0, %1, %2;" : "=l"(d) : "l"(a), "l"(b)); return d;
}
__device__ __forceinline__ ull f2x_fma(ull a, ull b, ull c) {
    ull d; asm("fma.rn.f32x2 %0, %1, %2, %3;" : "=l"(d) : "l"(a), "l"(b), "l"(c)); return d;
}
__device__ __forceinline__ ull packff(float x, float y) {
    ull d; asm("mov.b64 %0, {%1, %2};" : "=l"(d) : "f"(x), "f"(y)); return d;
}
__device__ __forceinline__ void unpackff(ull v, float& x, float& y) {
    asm("mov.b64 {%0, %1}, %2;" : "=f"(x), "=f"(y) : "l"(v));
}
__device__ __forceinline__ void prefetchL1(const void* p) {
    asm volatile("prefetch.global.L1 [%0];" :: "l"(p));
}

// ---------------------------------------------------------------- bit packing
__global__ void pack_bits_kernel(const int* __restrict__ cfg) {
    int t = blockIdx.x * blockDim.x + threadIdx.x;
    int row = t >> 3, w = t & 7;
    const int* p = cfg + row * NSITES + w * 32;
    unsigned int v = 0;
#pragma unroll
    for (int b = 0; b < 32; b++) v |= ((unsigned int)p[b] & 1u) << b;
    g_bits[row * 8 + w] = v;
}

// ------------- pair-product table, compensated, correctly-rounded fp32 output
// (arithmetic identical to R11's build — do not touch: G bits define rel_err)
__global__ void build_G_kernel(const float* __restrict__ bulk) {
    __shared__ float As[64 * 65];
    __shared__ float Bs[64 * 68];
    int g = blockIdx.x, c = blockIdx.y;
    int v0 = c & 1, v1 = (c >> 1) & 1;
    int tid = threadIdx.x;
    const float* A = bulk + (size_t)(2 * g) * 8192 + v0 * 64;   // bulk[2g][i][v0][j]
    const float* B = bulk + (size_t)(2 * g + 1) * 8192 + v1 * 64;
    for (int n = tid; n < 4096; n += 256) {
        int i = n >> 6, j = n & 63;
        As[i * 65 + j] = A[i * 128 + j];
        Bs[i * 68 + j] = B[i * 128 + j];
    }
    __syncthreads();
    int r  = tid >> 2;
    int j0 = (tid & 3) * 16;
    float s[16], cc[16], ae[16];
#pragma unroll
    for (int q = 0; q < 16; q++) { s[q] = 0.f; cc[q] = 0.f; ae[q] = 0.f; }
#pragma unroll 8
    for (int k = 0; k < 64; k++) {
        float a = As[r * 65 + k];
#pragma unroll
        for (int q = 0; q < 16; q++) {
            float b  = Bs[k * 68 + j0 + q];
            float p  = a * b;
            float e1 = fmaf(a, b, -p);
            float y  = p - cc[q];
            float t  = s[q] + y;
            cc[q]    = (t - s[q]) - y;
            s[q]     = t;
            ae[q]   += e1;
        }
    }
    size_t base = ((size_t)(g * 4 + c) << 12) + r * 64 + j0;
#pragma unroll
    for (int q = 0; q < 16; q++)
        g_Gh[base + q] = s[q] + (ae[q] - cc[q]);    // ~correctly rounded
}

// --------------------------------------------------------------- main chain
__global__ __launch_bounds__(16 * SPC, 1)
void mps_main_kernel(const float* __restrict__ left,
                     const float* __restrict__ right,
                     float* __restrict__ out) {
    const int tid  = threadIdx.x;
    const int o    = tid & 15;                   // lane group: cols [4o,4o+4)
    const int row0 = blockIdx.x * SPC + (tid >> 4);
    const int row  = row0 < BATCH ? row0 : BATCH - 1;

    unsigned int B[8];
#pragma unroll
    for (int w = 0; w < 8; w++) B[w] = g_bits[row * 8 + w];
#define BIT(s) ((B[(s) >> 5] >> ((s) & 31)) & 1u)

    float env[4];
    {
        unsigned int b0 = BIT(0);
#pragma unroll
        for (int t = 0; t < 4; t++) env[t] = left[b0 * 64 + 4 * o + t];
    }
    int ls2 = 0;

    for (int g = 0; g < NGROUP; g++) {
        unsigned int c = BIT(2 * g + 1) | (BIT(2 * g + 2) << 1);
        const float* __restrict__ Gm = g_Gh + ((size_t)(g * 4 + c) << 12) + 4 * o;

        // early prefetch of NEXT group's head lines (register-only address,
        // no arithmetic effect) — warms L1 across this group's whole dot.
        if (g + 1 < NGROUP) {
            unsigned int cn = BIT(2 * g + 3) | (BIT(2 * g + 4) << 1);
            const float* Gn = g_Gh + ((size_t)((g + 1) * 4 + cn) << 12) + 4 * o;
#pragma unroll
            for (int pr = 0; pr < 8; pr++)
                prefetchL1(Gn + (pr << 6));
        }

        ull s[2], nc[2], lo[2];
#pragma unroll
        for (int u = 0; u < 2; u++) { s[u] = 0ULL; nc[u] = 0ULL; lo[u] = 0ULL; }

#pragma unroll
        for (int i = 0; i < 64; i++) {               // FULL unroll (same order)
            float eh = __shfl_sync(0xFFFFFFFFu, env[i & 3], i >> 2, 16);
            ull ep = packff(eh, eh);
            float4 h0 = *(const float4*)(Gm + (i << 6));
            ull h2[2] = { packff(h0.x, h0.y), packff(h0.z, h0.w) };
#pragma unroll
            for (int u = 0; u < 2; u++) {
                ull p  = f2x_mul(ep, h2[u]);
                ull e1 = f2x_fma(ep, h2[u], p ^ SGN64);        // exact prod err
                lo[u]  = f2x_add(lo[u], e1);
                ull y  = f2x_add(p, nc[u]);                    // p - c
                ull t  = f2x_add(s[u], y);
                nc[u]  = f2x_add(f2x_add(s[u], t ^ SGN64), y); // -(new c)
                s[u]   = t;
            }
        }

        // fold s + nc + lo -> env; track group max (same order as R11)
        float m = 0.0f;
#pragma unroll
        for (int u = 0; u < 2; u++) {
            ull tot = f2x_add(s[u], f2x_add(nc[u], lo[u]));
            unpackff(tot, env[2 * u], env[2 * u + 1]);
            m = fmaxf(m, fmaxf(fabsf(env[2 * u]), fabsf(env[2 * u + 1])));
        }

        // exact power-of-2 rescale (16-lane max stays within the sample)
        m = fmaxf(m, __shfl_xor_sync(0xFFFFFFFFu, m, 1, 16));
        m = fmaxf(m, __shfl_xor_sync(0xFFFFFFFFu, m, 2, 16));
        m = fmaxf(m, __shfl_xor_sync(0xFFFFFFFFu, m, 4, 16));
        m = fmaxf(m, __shfl_xor_sync(0xFFFFFFFFu, m, 8, 16));
        int ef = (int)(__float_as_uint(m) >> 23);
        if (ef > 0) {
            ls2 += ef - 127;
            float sc = __uint_as_float((unsigned int)(254 - ef) << 23);
#pragma unroll
            for (int t = 0; t < 4; t++) env[t] *= sc;
        }
    }

    // final contraction in fp64 (cancellation-sensitive, one-shot)
    unsigned int bl = BIT(255);
    double part = 0.0;
#pragma unroll
    for (int t = 0; t < 4; t++)
        part = fma((double)env[t], (double)right[(4 * o + t) * 2 + bl], part);
    part += __shfl_xor_sync(0xFFFFFFFFu, part, 1, 16);
    part += __shfl_xor_sync(0xFFFFFFFFu, part, 2, 16);
    part += __shfl_xor_sync(0xFFFFFFFFu, part, 4, 16);
    part += __shfl_xor_sync(0xFFFFFFFFu, part, 8, 16);

    if (o == 0 && row0 < BATCH) {
        double ap = fabs(part);
        if (ap < 1e-300) ap = 1e-300;
        out[row0] = (float)(2.0 * (log(ap) + (double)ls2 * 0.6931471805599453094));
    }
#undef BIT
}

// ------------------------------------------------------------------- launch
extern "C" void kernel_launch(void* const* d_in, const int* in_sizes, int n_in,
                              void* d_out, int out_size) {
    const int*   cfg   = (const int*)d_in[0];
    const float* left  = (const float*)d_in[1];
    const float* bulk  = (const float*)d_in[2];
    const float* right = (const float*)d_in[3];
    float*       out   = (float*)d_out;

    pack_bits_kernel<<<BATCH * 8 / 256, 256>>>(cfg);
    dim3 gg(NGROUP, 4);
    build_G_kernel<<<gg, 256>>>(bulk);
    mps_main_kernel<<<(BATCH + SPC - 1) / SPC, 16 * SPC>>>(left, right, out);
}